// round 15
// baseline (speedup 1.0000x reference)
#include <cuda_runtime.h>
#include <cuda_fp16.h>
#include <cuda_bf16.h>
#include <cstdint>

#define NE 20000
#define NN 1000

// permuted row order: m=0 rows(5), +1(4), -1(4), +2(3), -2(3)
__constant__ int c_PERM[19]   = {0,2,6,11,16, 3,7,12,17, 1,5,10,15, 8,13,18, 4,9,14};
__constant__ int c_RADOFF[19] = {0,128,256,384,512, 640,768,896,1024, 640,768,896,1024,
                                 1152,1280,1408, 1152,1280,1408};

// ----------------- scratch (__device__ globals; no runtime alloc) -----------
__device__ __align__(16) __half g_hid [(size_t)NE*64];
__device__ __align__(16) __half g_rad [(size_t)NE*1536];
__device__ __align__(16) __half g_sm  [(size_t)NE*2432];
__device__ __align__(16) float  g_tmp0[(size_t)NE*896];
__device__ __align__(16) __half g_h1  [(size_t)NE*1216];
__device__ __align__(16) __half g_h2  [(size_t)NE*1216];
__device__ __align__(16) __half g_h3  [(size_t)NE*2432];
__device__ __align__(16) float  g_alf [(size_t)NE*8];
__device__ __align__(16) float  g_node[(size_t)NN*3200];
__device__ int g_cnt[NN+1];
__device__ int g_cur[NN];
__device__ int g_csr[NE];
// fp16-prepped weights (plain + complex-expanded)
__device__ __align__(16) __half g_wp [2514944];

#define WP_RAD   0
#define WP_C1G0  98304
#define WP_C1M1  671744
#define WP_C1M2  1196032
#define WP_C2G0  1490944
#define WP_C2M1  1695744
#define WP_C2M2  2220032

// ----------------- helpers --------------------------------------------------
__device__ __forceinline__ float sigmoidf_(float x){ return 1.f/(1.f+__expf(-x)); }
__device__ __forceinline__ float siluf_(float x){ return x*sigmoidf_(x); }
__device__ __forceinline__ float slrelu_(float x){ return 0.6f*x + 0.4f*x*(2.f*sigmoidf_(x)-1.f); }

// packed dual-fp32 FMA: d = a*b + d
__device__ __forceinline__ void fma2_(unsigned long long &d,
                                      unsigned long long a, unsigned long long b){
    asm("fma.rn.f32x2 %0, %1, %2, %0;" : "+l"(d) : "l"(a), "l"(b));
}
__device__ __forceinline__ unsigned long long pk2_(float a, float b){
    unsigned long long r;
    asm("mov.b64 %0, {%1, %2};" : "=l"(r) : "f"(a), "f"(b));
    return r;
}
__device__ __forceinline__ float2 up2_(unsigned long long v){
    float2 r;
    asm("mov.b64 {%0, %1}, %2;" : "=f"(r.x), "=f"(r.y) : "l"(v));
    return r;
}

__device__ __forceinline__ void mma16h(float* d, const unsigned* a, const unsigned* b){
    asm("mma.sync.aligned.m16n8k16.row.col.f32.f16.f16.f32 "
        "{%0,%1,%2,%3}, {%4,%5,%6,%7}, {%8,%9}, {%0,%1,%2,%3};"
        : "+f"(d[0]), "+f"(d[1]), "+f"(d[2]), "+f"(d[3])
        : "r"(a[0]), "r"(a[1]), "r"(a[2]), "r"(a[3]), "r"(b[0]), "r"(b[1]));
}

__device__ __forceinline__ float red64(float v, float* sbuf, int t){
    #pragma unroll
    for (int o=16;o;o>>=1) v += __shfl_xor_sync(0xffffffffu, v, o);
    if ((t&31)==0) sbuf[t>>5] = v;
    __syncthreads();
    float r = sbuf[0]+sbuf[1];
    __syncthreads();
    return r;
}

// ----------------- CSR build ------------------------------------------------
__global__ void k_zeroc(int* cnt){
    int i = blockIdx.x*256 + threadIdx.x;
    if (i <= NN) cnt[i] = 0;
}
__global__ void k_count(const int* __restrict__ ei, int* cnt){
    int i = blockIdx.x*256 + threadIdx.x;
    if (i < NE) atomicAdd(&cnt[ei[NE + i]], 1);
}
__global__ void k_scan(int* cnt, int* cur){
    __shared__ int s[1024];
    int t = threadIdx.x;
    int v = (t < NN) ? cnt[t] : 0;
    s[t] = v;
    __syncthreads();
    for (int o = 1; o < 1024; o <<= 1) {
        int x = (t >= o) ? s[t - o] : 0;
        __syncthreads();
        s[t] += x;
        __syncthreads();
    }
    int incl = s[t];
    if (t < NN) { cnt[t] = incl - v; cur[t] = incl - v; }
    if (t == NN - 1) cnt[NN] = incl;
}
__global__ void k_scatter(const int* __restrict__ ei, int* cur, int* csr){
    int i = blockIdx.x*256 + threadIdx.x;
    if (i < NE) {
        int pos = atomicAdd(&cur[ei[NE + i]], 1);
        csr[pos] = i;
    }
}

// ----------------- weight prep ----------------------------------------------
__global__ void k_cvtw(const float* __restrict__ w, __half* __restrict__ o, int n){
    int i = blockIdx.x*256 + threadIdx.x;
    if (i < n) o[i] = __float2half_rn(w[i]);
}
__global__ void k_prepw(const float* __restrict__ w, __half* __restrict__ wp, int N, int K){
    int i = blockIdx.x*256 + threadIdx.x;
    if (i >= N*K) return;
    int n = i / K, k = i % K;
    float wr = w[(size_t)n*K + k];
    float wi = w[(size_t)(N+n)*K + k];
    size_t row0 = (size_t)n*2*K, row1 = (size_t)(N+n)*2*K;
    wp[row0 + k]     = __float2half_rn(wr);
    wp[row0 + K + k] = __float2half_rn(-wi);
    wp[row1 + k]     = __float2half_rn(wi);
    wp[row1 + K + k] = __float2half_rn(wr);
}

// ----------------- radial layers 1+2 (LN + silu) ----------------------------
__global__ void k_radial(const float* __restrict__ ed,
                         const float* __restrict__ w1, const float* __restrict__ b1,
                         const float* __restrict__ g1, const float* __restrict__ be1,
                         const float* __restrict__ w2, const float* __restrict__ b2,
                         const float* __restrict__ g2, const float* __restrict__ be2,
                         __half* __restrict__ outp)
{
    __shared__ float w1t[64*64], w2t[64*64];
    __shared__ float xin[64], hmid[64];
    __shared__ float sbuf[2];
    int t = threadIdx.x; // 64
    for (int i = t; i < 4096; i += 64) {
        int r = i >> 6, c = i & 63;
        w1t[c*64 + r] = w1[i];
        w2t[c*64 + r] = w2[i];
    }
    __syncthreads();
    for (int e = blockIdx.x; e < NE; e += gridDim.x) {
        xin[t] = ed[(size_t)e*64 + t];
        __syncthreads();
        float acc = b1[t];
        #pragma unroll 8
        for (int k = 0; k < 64; k++) acc += xin[k]*w1t[k*64+t];
        float mu = red64(acc, sbuf, t) * (1.f/64.f);
        float d = acc - mu;
        float var = red64(d*d, sbuf, t) * (1.f/64.f);
        float v = d*rsqrtf(var+1e-5f)*g1[t] + be1[t];
        hmid[t] = siluf_(v);
        __syncthreads();
        acc = b2[t];
        #pragma unroll 8
        for (int k = 0; k < 64; k++) acc += hmid[k]*w2t[k*64+t];
        mu = red64(acc, sbuf, t) * (1.f/64.f);
        d = acc - mu;
        var = red64(d*d, sbuf, t) * (1.f/64.f);
        v = d*rsqrtf(var+1e-5f)*g2[t] + be2[t];
        outp[(size_t)e*64 + t] = __float2half_rn(siluf_(v));
        __syncthreads();
    }
}

// ======= merged fp16 tensor-core GEMM launcher ==============================
struct GDesc {
    const __half* A; const __half* W; const float* bias;
    __half* Ch; float* Cf;
    int lda, ldc, K, ohalf;
};
struct GPack { GDesc d[3]; int cum1, cum2; };

#define GH_ASTRIDE 264
#define GH_BSTRIDE 136
#define GH_BOFF    (2*8*GH_ASTRIDE)
#define GH_SMEM    ((2*8*GH_ASTRIDE + 2*8*GH_BSTRIDE)*4)

__global__ void __launch_bounds__(256) k_gemm_m(GPack gp, int M)
{
    extern __shared__ __align__(16) unsigned smemu[];
    unsigned (*As2)[8][GH_ASTRIDE] = (unsigned(*)[8][GH_ASTRIDE])smemu;
    unsigned (*Bs2)[8][GH_BSTRIDE] = (unsigned(*)[8][GH_BSTRIDE])(smemu + GH_BOFF);
    const int tid = threadIdx.x;
    const int x = blockIdx.x;
    const int gi = (x >= gp.cum1) + (x >= gp.cum2);
    const GDesc dsc = gp.d[gi];
    const int base = gi == 0 ? 0 : (gi == 1 ? gp.cum1 : gp.cum2);
    const int bm = blockIdx.y*256, bn = (x - base)*128;
    const __half* __restrict__ A = dsc.A;
    const __half* __restrict__ W = dsc.W;
    const int lda = dsc.lda, K = dsc.K;
    const int wid = tid >> 5, lane = tid & 31;
    const int wm = wid & 3, wn = wid >> 2;
    const int g = lane >> 2, q = lane & 3;
    const int srow = tid >> 2, sq4 = tid & 3;

    float acc[4][8][4];
    #pragma unroll
    for (int i=0;i<4;i++)
        #pragma unroll
        for (int j=0;j<8;j++)
            #pragma unroll
            for (int r=0;r<4;r++) acc[i][j][r] = 0.f;

    #define HSTAGE_A(buf, k0) { \
        _Pragma("unroll") \
        for (int i = 0; i < 4; i++) { \
            int row = srow + 64*i; \
            uint2 v = make_uint2(0u, 0u); \
            if (bm + row < M) v = *(const uint2*)(A + (size_t)(bm+row)*lda + (k0) + sq4*4); \
            As2[buf][sq4*2+0][row] = v.x; \
            As2[buf][sq4*2+1][row] = v.y; \
        } }
    #define HSTAGE_B(buf, k0) { \
        _Pragma("unroll") \
        for (int i = 0; i < 2; i++) { \
            int row = srow + 64*i; \
            uint2 v = *(const uint2*)(W + (size_t)(bn+row)*K + (k0) + sq4*4); \
            Bs2[buf][sq4*2+0][row] = v.x; \
            Bs2[buf][sq4*2+1][row] = v.y; \
        } }

    HSTAGE_A(0, 0)
    HSTAGE_B(0, 0)
    __syncthreads();

    const int nit = K >> 4;
    int buf = 0;
    for (int it = 0; it < nit; it++) {
        uint2 pa[4], pb[2];
        const bool more = (it + 1 < nit);
        if (more) {
            int k0 = (it + 1) << 4;
            #pragma unroll
            for (int i = 0; i < 4; i++) {
                int row = srow + 64*i;
                pa[i] = make_uint2(0u, 0u);
                if (bm + row < M) pa[i] = *(const uint2*)(A + (size_t)(bm+row)*lda + k0 + sq4*4);
            }
            #pragma unroll
            for (int i = 0; i < 2; i++) {
                int row = srow + 64*i;
                pb[i] = *(const uint2*)(W + (size_t)(bn+row)*K + k0 + sq4*4);
            }
        }
        {
            unsigned af[4][4];
            #pragma unroll
            for (int mt=0; mt<4; mt++){
                int mb = wm*64 + mt*16;
                af[mt][0] = As2[buf][q  ][mb+g  ];
                af[mt][1] = As2[buf][q  ][mb+g+8];
                af[mt][2] = As2[buf][q+4][mb+g  ];
                af[mt][3] = As2[buf][q+4][mb+g+8];
            }
            unsigned bf[8][2];
            #pragma unroll
            for (int nt=0; nt<8; nt++){
                int nb = wn*64 + nt*8;
                bf[nt][0] = Bs2[buf][q  ][nb+g];
                bf[nt][1] = Bs2[buf][q+4][nb+g];
            }
            #pragma unroll
            for (int mt=0; mt<4; mt++)
                #pragma unroll
                for (int nt=0; nt<8; nt++)
                    mma16h(acc[mt][nt], af[mt], bf[nt]);
        }
        if (more) {
            int nb2 = buf ^ 1;
            #pragma unroll
            for (int i = 0; i < 4; i++) {
                int row = srow + 64*i;
                As2[nb2][sq4*2+0][row] = pa[i].x;
                As2[nb2][sq4*2+1][row] = pa[i].y;
            }
            #pragma unroll
            for (int i = 0; i < 2; i++) {
                int row = srow + 64*i;
                Bs2[nb2][sq4*2+0][row] = pb[i].x;
                Bs2[nb2][sq4*2+1][row] = pb[i].y;
            }
            __syncthreads();
            buf = nb2;
        }
    }
    const int ldc = dsc.ldc;
    #pragma unroll
    for (int nt=0; nt<8; nt++) {
        int c = bn + wn*64 + nt*8 + q*2;
        float2 bv = make_float2(0.f, 0.f);
        if (dsc.bias) bv = *(const float2*)(dsc.bias + c);
        #pragma unroll
        for (int mt=0; mt<4; mt++) {
            int r0 = bm + wm*64 + mt*16 + g;
            if (r0 < M) {
                float ox = acc[mt][nt][0]+bv.x, oy = acc[mt][nt][1]+bv.y;
                if (dsc.ohalf) *(__half2*)(dsc.Ch + (size_t)r0*ldc + c) = __floats2half2_rn(ox, oy);
                else           *(float2*)(dsc.Cf + (size_t)r0*ldc + c) = make_float2(ox, oy);
            }
            if (r0 + 8 < M) {
                float ox = acc[mt][nt][2]+bv.x, oy = acc[mt][nt][3]+bv.y;
                if (dsc.ohalf) *(__half2*)(dsc.Ch + (size_t)(r0+8)*ldc + c) = __floats2half2_rn(ox, oy);
                else           *(float2*)(dsc.Cf + (size_t)(r0+8)*ldc + c) = make_float2(ox, oy);
            }
        }
    }
}

// ---------- wigner: msg = perm(wigner @ [x_src|x_dst]) * rad ----------------
__global__ void k_wigner(const float* __restrict__ x, const int* __restrict__ ei,
                         const float* __restrict__ wig, const __half* __restrict__ rad,
                         __half* __restrict__ sm)
{
    __shared__ __align__(16) float wg[19][28];
    int e = blockIdx.x;
    int t = threadIdx.x; // 128
    int src = ei[e], dst = ei[NE + e];
    const float* xp = (t < 64) ? (x + (size_t)src*1600) : (x + (size_t)dst*1600);
    int c = t & 63;
    float msg[28];
    #pragma unroll
    for (int j = 0; j < 25; j++) msg[j] = xp[j*64 + c];
    msg[25] = 0.f; msg[26] = 0.f; msg[27] = 0.f;
    for (int i = t; i < 475; i += 128) {
        int p = i/25, j = i%25;
        wg[p][j] = wig[(size_t)e*475 + (size_t)c_PERM[p]*25 + j];
    }
    for (int i = t; i < 57; i += 128) {          // zero the 3-pad per row
        int p = i/3, j = 25 + i%3;
        wg[p][j] = 0.f;
    }
    __syncthreads();
    const __half* re = rad + (size_t)e*1536;
    __half* so = sm + (size_t)e*2432;
    #pragma unroll
    for (int p = 0; p < 19; p++) {
        float acc = 0.f;
        #pragma unroll
        for (int j4 = 0; j4 < 7; j4++) {
            float4 w4 = *(const float4*)&wg[p][j4*4];
            acc += w4.x*msg[j4*4+0] + w4.y*msg[j4*4+1]
                 + w4.z*msg[j4*4+2] + w4.w*msg[j4*4+3];
        }
        so[p*128 + t] = __float2half_rn(acc * __half2float(re[c_RADOFF[p] + t]));
    }
}

// ---------- grid stage: f32x2-packed silu-gated S2 pointwise ----------------
// 4 edges/block; each thread owns 2 adjacent channels of one edge.
// tg/fg stored as duplicated float2 pairs -> ulonglong2 LDS feeds 2 fma.f32x2.
__global__ void k_grid(const float* __restrict__ tmp0, const __half* __restrict__ h1,
                       const float* __restrict__ tgrid, const float* __restrict__ fgrid,
                       __half* __restrict__ h2)
{
    __shared__ __align__(16) float2 tgd[100][20];
    __shared__ __align__(16) float2 fgd[100][20];
    int t = threadIdx.x; // 128
    for (int i = t; i < 2000; i += 128) {
        int ba = i / 20, p = i % 20;
        float tv = (p < 19) ? tgrid[ba*19 + c_PERM[p]] : 0.f;
        float fv = (p < 19) ? fgrid[ba*19 + c_PERM[p]] : 0.f;
        tgd[ba][p] = make_float2(tv, tv);
        fgd[ba][p] = make_float2(fv, fv);
    }
    int el = t >> 5, c2 = t & 31;     // edge-in-block, channel-pair
    int e = blockIdx.x*4 + el;
    const float* t0 = tmp0 + (size_t)e*896;
    unsigned long long hreg[20];
    #pragma unroll
    for (int p = 0; p < 5; p++) {
        float2 v = *(const float2*)(t0 + 576 + p*64 + 2*c2);
        hreg[p] = pk2_(v.x, v.y);
    }
    const __half* hh = h1 + (size_t)e*1216;
    #pragma unroll
    for (int p = 5; p < 19; p++) {
        float2 f = __half22float2(*(const __half2*)(hh + p*64 + 2*c2));
        hreg[p] = pk2_(f.x, f.y);
    }
    hreg[19] = 0ull;
    __syncthreads();
    unsigned long long s2[20];
    #pragma unroll
    for (int p=0;p<20;p++) s2[p]=0ull;
    for (int ba = 0; ba < 100; ba++) {
        unsigned long long g2 = 0ull;
        #pragma unroll
        for (int p2 = 0; p2 < 10; p2++) {
            ulonglong2 tp = *(const ulonglong2*)&tgd[ba][2*p2];
            fma2_(g2, tp.x, hreg[2*p2]);
            fma2_(g2, tp.y, hreg[2*p2+1]);
        }
        float2 gf = up2_(g2);
        unsigned long long gs = pk2_(siluf_(gf.x), siluf_(gf.y));
        #pragma unroll
        for (int p2 = 0; p2 < 10; p2++) {
            ulonglong2 fp = *(const ulonglong2*)&fgd[ba][2*p2];
            fma2_(s2[2*p2],   fp.x, gs);
            fma2_(s2[2*p2+1], fp.y, gs);
        }
    }
    __half* o = h2 + (size_t)e*1216;
    {
        float2 gt = *(const float2*)(t0 + 512 + 2*c2);
        *(__half2*)(o + 2*c2) = __floats2half2_rn(siluf_(gt.x), siluf_(gt.y));
    }
    #pragma unroll
    for (int p = 1; p < 19; p++) {
        float2 sv = up2_(s2[p]);
        *(__half2*)(o + p*64 + 2*c2) = __floats2half2_rn(sv.x, sv.y);
    }
}

// ---------- alpha logits: LN + smooth-leaky-relu + dot ----------------------
__global__ void k_alpha1(const float* __restrict__ tmp0,
                         const float* __restrict__ lng, const float* __restrict__ lnb,
                         const float* __restrict__ adot,
                         float* __restrict__ alpha)
{
    int e = blockIdx.x;
    int w = threadIdx.x >> 5, lane = threadIdx.x & 31; // 8 warps = 8 heads
    const float* a = tmp0 + (size_t)e*896 + w*64;
    float v0 = a[lane], v1 = a[lane+32];
    float s = v0+v1;
    #pragma unroll
    for (int o=16;o;o>>=1) s += __shfl_xor_sync(0xffffffffu, s, o);
    float mu = s * (1.f/64.f);
    float d0=v0-mu, d1=v1-mu;
    float q = d0*d0+d1*d1;
    #pragma unroll
    for (int o=16;o;o>>=1) q += __shfl_xor_sync(0xffffffffu, q, o);
    float rstd = rsqrtf(q*(1.f/64.f) + 1e-5f);
    float x0 = slrelu_(d0*rstd*lng[lane]+lnb[lane]);
    float x1 = slrelu_(d1*rstd*lng[lane+32]+lnb[lane+32]);
    float p = x0*adot[w*64+lane] + x1*adot[w*64+lane+32];
    #pragma unroll
    for (int o=16;o;o>>=1) p += __shfl_xor_sync(0xffffffffu, p, o);
    if (lane == 0) alpha[e*8+w] = p;
}

// ---------- per-node attention: softmax + wigner_inv + direct sum -----------
__global__ void k_attn(const __half* __restrict__ h3, const float* __restrict__ winv,
                       const float* __restrict__ alpha,
                       const int* __restrict__ cnt, const int* __restrict__ csr,
                       float* __restrict__ node)
{
    __shared__ __align__(16) float wi[25][20];
    __shared__ float wt8[8];
    __shared__ float mx[8], dn[8];
    int n = blockIdx.x, t = threadIdx.x; // 128
    int off = cnt[n], deg = cnt[n+1] - off;
    if (t < 8) {
        float m = -1e30f;
        for (int i = 0; i < deg; i++) m = fmaxf(m, alpha[csr[off+i]*8 + t]);
        mx[t] = m;
        float s = 0.f;
        for (int i = 0; i < deg; i++) s += __expf(alpha[csr[off+i]*8 + t] - m);
        dn[t] = s;
    }
    if (t < 25) wi[t][19] = 0.f;      // zero pad column
    __syncthreads();
    float acc[25];
    #pragma unroll
    for (int r = 0; r < 25; r++) acc[r] = 0.f;
    for (int i = 0; i < deg; i++) {
        int e = csr[off + i];
        for (int j = t; j < 475; j += 128) {
            int r = j/19, p = j%19;
            wi[r][p] = winv[(size_t)e*475 + r*19 + c_PERM[p]];
        }
        if (t < 8) wt8[t] = __expf(alpha[e*8+t] - mx[t]) / (dn[t] + 1e-16f);
        __syncthreads();
        float w = wt8[t >> 4];
        const __half* hh = h3 + (size_t)e*2432;
        float m[20];
        #pragma unroll
        for (int p = 0; p < 19; p++) m[p] = __half2float(hh[p*128 + t]) * w;
        m[19] = 0.f;
        #pragma unroll
        for (int r = 0; r < 25; r++) {
            float a = 0.f;
            #pragma unroll
            for (int p4 = 0; p4 < 5; p4++) {
                float4 w4 = *(const float4*)&wi[r][4*p4];
                a += w4.x*m[4*p4] + w4.y*m[4*p4+1] + w4.z*m[4*p4+2] + w4.w*m[4*p4+3];
            }
            acc[r] += a;
        }
        __syncthreads();
    }
    float* no = node + (size_t)n*3200;
    #pragma unroll
    for (int r = 0; r < 25; r++) no[r*128 + t] = acc[r];
}

// ---------- output projection ----------------------------------------------
__global__ void k_proj(const float* __restrict__ node, const float* __restrict__ pw,
                       const float* __restrict__ pb, float* __restrict__ outp)
{
    __shared__ float wt[128*65];
    int bid = blockIdx.x;      // n*5 + l
    int n = bid / 5, l = bid % 5;
    int t = threadIdx.x;       // 64
    for (int i = t; i < 8192; i += 64) {
        int o = i >> 7, c = i & 127;
        wt[c*65 + o] = pw[l*8192 + i];
    }
    __syncthreads();
    int i0 = l*l, i1 = (l+1)*(l+1);
    for (int i = i0; i < i1; i++) {
        const float* nr = node + (size_t)n*3200 + i*128;
        float acc = (i == 0) ? pb[t] : 0.f;
        #pragma unroll 8
        for (int c = 0; c < 128; c++) acc += nr[c] * wt[c*65 + t];
        outp[(size_t)n*1600 + i*64 + t] = acc;
    }
}

// ----------------------------------------------------------------------------
extern "C" void kernel_launch(void* const* d_in, const int* in_sizes, int n_in,
                              void* d_out, int out_size)
{
    const float* x    = (const float*)d_in[0];
    const float* ed   = (const float*)d_in[1];
    const int*   ei   = (const int*)  d_in[2];
    const float* wig  = (const float*)d_in[3];
    const float* winv = (const float*)d_in[4];
    const float* tgr  = (const float*)d_in[5];
    const float* fgr  = (const float*)d_in[6];
    const float* rw1  = (const float*)d_in[7];
    const float* rb1  = (const float*)d_in[8];
    const float* rg1  = (const float*)d_in[9];
    const float* rbe1 = (const float*)d_in[10];
    const float* rw2  = (const float*)d_in[11];
    const float* rb2  = (const float*)d_in[12];
    const float* rg2  = (const float*)d_in[13];
    const float* rbe2 = (const float*)d_in[14];
    const float* rw3  = (const float*)d_in[15];
    const float* rb3  = (const float*)d_in[16];
    const float* c1w0 = (const float*)d_in[17];
    const float* c1b0 = (const float*)d_in[18];
    const float* c1w1 = (const float*)d_in[19];
    const float* c1w2 = (const float*)d_in[20];
    const float* c2w0 = (const float*)d_in[21];
    const float* c2b0 = (const float*)d_in[22];
    const float* c2w1 = (const float*)d_in[23];
    const float* c2w2 = (const float*)d_in[24];
    const float* alng = (const float*)d_in[25];
    const float* alnb = (const float*)d_in[26];
    const float* adot = (const float*)d_in[27];
    const float* pw   = (const float*)d_in[28];
    const float* pb   = (const float*)d_in[29];
    float* outp = (float*)d_out;

    void* p;
    cudaGetSymbolAddress(&p, g_hid);  __half* hid = (__half*)p;
    cudaGetSymbolAddress(&p, g_rad);  __half* rad = (__half*)p;
    cudaGetSymbolAddress(&p, g_sm);   __half* sm  = (__half*)p;
    cudaGetSymbolAddress(&p, g_tmp0); float* tmp0 = (float*)p;
    cudaGetSymbolAddress(&p, g_h1);   __half* h1  = (__half*)p;
    cudaGetSymbolAddress(&p, g_h2);   __half* h2  = (__half*)p;
    cudaGetSymbolAddress(&p, g_h3);   __half* h3  = (__half*)p;
    cudaGetSymbolAddress(&p, g_alf);  float* alf  = (float*)p;
    cudaGetSymbolAddress(&p, g_node); float* node = (float*)p;
    cudaGetSymbolAddress(&p, g_wp);   __half* wp  = (__half*)p;
    cudaGetSymbolAddress(&p, g_cnt);  int* cnt = (int*)p;
    cudaGetSymbolAddress(&p, g_cur);  int* cur = (int*)p;
    cudaGetSymbolAddress(&p, g_csr);  int* csr = (int*)p;

    cudaFuncSetAttribute(k_gemm_m, cudaFuncAttributeMaxDynamicSharedMemorySize, GH_SMEM);

    const int MB = (NE + 255) / 256;   // 79
    const int BIG = 0x3fffffff;

    // CSR by destination
    k_zeroc<<<(NN + 256)/256, 256>>>(cnt);
    k_count<<<(NE + 255)/256, 256>>>(ei, cnt);
    k_scan<<<1, 1024>>>(cnt, cur);
    k_scatter<<<(NE + 255)/256, 256>>>(ei, cur, csr);

    // weight prep (fp16 round; complex weights expanded to real form)
    k_cvtw<<<(98304+255)/256, 256>>>(rw3,  wp + WP_RAD,  98304);
    k_cvtw<<<(573440+255)/256, 256>>>(c1w0, wp + WP_C1G0, 573440);
    k_cvtw<<<(204800+255)/256, 256>>>(c2w0, wp + WP_C2G0, 204800);
    k_prepw<<<(256*512+255)/256, 256>>>(c1w1, wp + WP_C1M1, 256, 512);
    k_prepw<<<(192*384+255)/256, 256>>>(c1w2, wp + WP_C1M2, 192, 384);
    k_prepw<<<(512*256+255)/256, 256>>>(c2w1, wp + WP_C2M1, 512, 256);
    k_prepw<<<(384*192+255)/256, 256>>>(c2w2, wp + WP_C2M2, 384, 192);

    k_radial<<<512, 64>>>(ed, rw1, rb1, rg1, rbe1, rw2, rb2, rg2, rbe2, hid);

    // radial layer 3 (fp16 out)
    {
        GPack gp{};
        gp.d[0] = GDesc{hid, wp + WP_RAD, rb3, rad, nullptr, 64, 1536, 64, 1};
        gp.cum1 = BIG; gp.cum2 = BIG;
        k_gemm_m<<<dim3(12, MB), 256, GH_SMEM>>>(gp, NE);
    }
    k_wigner<<<NE, 128>>>(x, ei, wig, rad, sm);
    // conv1: 3 gemms merged
    {
        GPack gp{};
        gp.d[0] = GDesc{sm,      wp + WP_C1G0, c1b0,    nullptr, tmp0, 2432, 896, 640, 0};
        gp.d[1] = GDesc{sm+640,  wp + WP_C1M1, nullptr, h1+320, nullptr, 2432, 1216, 1024, 1};
        gp.d[2] = GDesc{sm+1664, wp + WP_C1M2, nullptr, h1+832, nullptr, 2432, 1216, 768, 1};
        gp.cum1 = 7; gp.cum2 = 11;
        k_gemm_m<<<dim3(14, MB), 256, GH_SMEM>>>(gp, NE);
    }
    k_grid<<<NE/4, 128>>>(tmp0, h1, tgr, fgr, h2);
    // conv2: 3 gemms merged
    {
        GPack gp{};
        gp.d[0] = GDesc{h2,     wp + WP_C2G0, c2b0,    h3,      nullptr, 1216, 2432, 320, 1};
        gp.d[1] = GDesc{h2+320, wp + WP_C2M1, nullptr, h3+640,  nullptr, 1216, 2432, 512, 1};
        gp.d[2] = GDesc{h2+832, wp + WP_C2M2, nullptr, h3+1664, nullptr, 1216, 2432, 384, 1};
        gp.cum1 = 5; gp.cum2 = 13;
        k_gemm_m<<<dim3(19, MB), 256, GH_SMEM>>>(gp, NE);
    }
    // attention (per-node, no atomics)
    k_alpha1<<<NE, 256>>>(tmp0, alng, alnb, adot, alf);
    k_attn<<<NN, 128>>>(h3, winv, alf, cnt, csr, node);
    // projection
    k_proj<<<NN*5, 64>>>(node, pw, pb, outp);
}

// round 16
// speedup vs baseline: 1.0113x; 1.0113x over previous
#include <cuda_runtime.h>
#include <cuda_fp16.h>
#include <cuda_bf16.h>
#include <cstdint>

#define NE 20000
#define NN 1000

// permuted row order: m=0 rows(5), +1(4), -1(4), +2(3), -2(3)
__constant__ int c_PERM[19]   = {0,2,6,11,16, 3,7,12,17, 1,5,10,15, 8,13,18, 4,9,14};
__constant__ int c_RADOFF[19] = {0,128,256,384,512, 640,768,896,1024, 640,768,896,1024,
                                 1152,1280,1408, 1152,1280,1408};

// ----------------- scratch (__device__ globals; no runtime alloc) -----------
__device__ __align__(16) __half g_hid [(size_t)NE*64];
__device__ __align__(16) __half g_rad [(size_t)NE*1536];
__device__ __align__(16) __half g_sm  [(size_t)NE*2432];
__device__ __align__(16) float  g_tmp0[(size_t)NE*896];
__device__ __align__(16) __half g_h1  [(size_t)NE*1216];
__device__ __align__(16) __half g_h2  [(size_t)NE*1216];
__device__ __align__(16) __half g_h3  [(size_t)NE*2432];
__device__ __align__(16) float  g_alf [(size_t)NE*8];
__device__ __align__(16) float  g_node[(size_t)NN*3200];
__device__ int g_cnt[NN+1];
__device__ int g_cur[NN];
__device__ int g_csr[NE];
// fp16-prepped weights (plain + complex-expanded)
__device__ __align__(16) __half g_wp [2514944];

#define WP_RAD   0
#define WP_C1G0  98304
#define WP_C1M1  671744
#define WP_C1M2  1196032
#define WP_C2G0  1490944
#define WP_C2M1  1695744
#define WP_C2M2  2220032

// ----------------- helpers --------------------------------------------------
__device__ __forceinline__ float sigmoidf_(float x){ return 1.f/(1.f+__expf(-x)); }
__device__ __forceinline__ float siluf_(float x){ return x*sigmoidf_(x); }
__device__ __forceinline__ float slrelu_(float x){ return 0.6f*x + 0.4f*x*(2.f*sigmoidf_(x)-1.f); }

__device__ __forceinline__ void mma16h(float* d, const unsigned* a, const unsigned* b){
    asm("mma.sync.aligned.m16n8k16.row.col.f32.f16.f16.f32 "
        "{%0,%1,%2,%3}, {%4,%5,%6,%7}, {%8,%9}, {%0,%1,%2,%3};"
        : "+f"(d[0]), "+f"(d[1]), "+f"(d[2]), "+f"(d[3])
        : "r"(a[0]), "r"(a[1]), "r"(a[2]), "r"(a[3]), "r"(b[0]), "r"(b[1]));
}

__device__ __forceinline__ float red64(float v, float* sbuf, int t){
    #pragma unroll
    for (int o=16;o;o>>=1) v += __shfl_xor_sync(0xffffffffu, v, o);
    if ((t&31)==0) sbuf[t>>5] = v;
    __syncthreads();
    float r = sbuf[0]+sbuf[1];
    __syncthreads();
    return r;
}

// ----------------- CSR build ------------------------------------------------
__global__ void k_zeroc(int* cnt){
    int i = blockIdx.x*256 + threadIdx.x;
    if (i <= NN) cnt[i] = 0;
}
__global__ void k_count(const int* __restrict__ ei, int* cnt){
    int i = blockIdx.x*256 + threadIdx.x;
    if (i < NE) atomicAdd(&cnt[ei[NE + i]], 1);
}
__global__ void k_scan(int* cnt, int* cur){
    __shared__ int s[1024];
    int t = threadIdx.x;
    int v = (t < NN) ? cnt[t] : 0;
    s[t] = v;
    __syncthreads();
    for (int o = 1; o < 1024; o <<= 1) {
        int x = (t >= o) ? s[t - o] : 0;
        __syncthreads();
        s[t] += x;
        __syncthreads();
    }
    int incl = s[t];
    if (t < NN) { cnt[t] = incl - v; cur[t] = incl - v; }
    if (t == NN - 1) cnt[NN] = incl;
}
__global__ void k_scatter(const int* __restrict__ ei, int* cur, int* csr){
    int i = blockIdx.x*256 + threadIdx.x;
    if (i < NE) {
        int pos = atomicAdd(&cur[ei[NE + i]], 1);
        csr[pos] = i;
    }
}

// ----------------- weight prep ----------------------------------------------
__global__ void k_cvtw(const float* __restrict__ w, __half* __restrict__ o, int n){
    int i = blockIdx.x*256 + threadIdx.x;
    if (i < n) o[i] = __float2half_rn(w[i]);
}
__global__ void k_prepw(const float* __restrict__ w, __half* __restrict__ wp, int N, int K){
    int i = blockIdx.x*256 + threadIdx.x;
    if (i >= N*K) return;
    int n = i / K, k = i % K;
    float wr = w[(size_t)n*K + k];
    float wi = w[(size_t)(N+n)*K + k];
    size_t row0 = (size_t)n*2*K, row1 = (size_t)(N+n)*2*K;
    wp[row0 + k]     = __float2half_rn(wr);
    wp[row0 + K + k] = __float2half_rn(-wi);
    wp[row1 + k]     = __float2half_rn(wi);
    wp[row1 + K + k] = __float2half_rn(wr);
}

// ----------------- radial layers 1+2 (LN + silu) ----------------------------
__global__ void k_radial(const float* __restrict__ ed,
                         const float* __restrict__ w1, const float* __restrict__ b1,
                         const float* __restrict__ g1, const float* __restrict__ be1,
                         const float* __restrict__ w2, const float* __restrict__ b2,
                         const float* __restrict__ g2, const float* __restrict__ be2,
                         __half* __restrict__ outp)
{
    __shared__ float w1t[64*64], w2t[64*64];
    __shared__ float xin[64], hmid[64];
    __shared__ float sbuf[2];
    int t = threadIdx.x; // 64
    for (int i = t; i < 4096; i += 64) {
        int r = i >> 6, c = i & 63;
        w1t[c*64 + r] = w1[i];
        w2t[c*64 + r] = w2[i];
    }
    __syncthreads();
    for (int e = blockIdx.x; e < NE; e += gridDim.x) {
        xin[t] = ed[(size_t)e*64 + t];
        __syncthreads();
        float acc = b1[t];
        #pragma unroll 8
        for (int k = 0; k < 64; k++) acc += xin[k]*w1t[k*64+t];
        float mu = red64(acc, sbuf, t) * (1.f/64.f);
        float d = acc - mu;
        float var = red64(d*d, sbuf, t) * (1.f/64.f);
        float v = d*rsqrtf(var+1e-5f)*g1[t] + be1[t];
        hmid[t] = siluf_(v);
        __syncthreads();
        acc = b2[t];
        #pragma unroll 8
        for (int k = 0; k < 64; k++) acc += hmid[k]*w2t[k*64+t];
        mu = red64(acc, sbuf, t) * (1.f/64.f);
        d = acc - mu;
        var = red64(d*d, sbuf, t) * (1.f/64.f);
        v = d*rsqrtf(var+1e-5f)*g2[t] + be2[t];
        outp[(size_t)e*64 + t] = __float2half_rn(siluf_(v));
        __syncthreads();
    }
}

// ======= merged fp16 tensor-core GEMM launcher ==============================
struct GDesc {
    const __half* A; const __half* W; const float* bias;
    __half* Ch; float* Cf;
    int lda, ldc, K, ohalf;
};
struct GPack { GDesc d[3]; int cum1, cum2; };

#define GH_ASTRIDE 264
#define GH_BSTRIDE 136
#define GH_BOFF    (2*8*GH_ASTRIDE)
#define GH_SMEM    ((2*8*GH_ASTRIDE + 2*8*GH_BSTRIDE)*4)

__global__ void __launch_bounds__(256) k_gemm_m(GPack gp, int M)
{
    extern __shared__ __align__(16) unsigned smemu[];
    unsigned (*As2)[8][GH_ASTRIDE] = (unsigned(*)[8][GH_ASTRIDE])smemu;
    unsigned (*Bs2)[8][GH_BSTRIDE] = (unsigned(*)[8][GH_BSTRIDE])(smemu + GH_BOFF);
    const int tid = threadIdx.x;
    const int x = blockIdx.x;
    const int gi = (x >= gp.cum1) + (x >= gp.cum2);
    const GDesc dsc = gp.d[gi];
    const int base = gi == 0 ? 0 : (gi == 1 ? gp.cum1 : gp.cum2);
    const int bm = blockIdx.y*256, bn = (x - base)*128;
    const __half* __restrict__ A = dsc.A;
    const __half* __restrict__ W = dsc.W;
    const int lda = dsc.lda, K = dsc.K;
    const int wid = tid >> 5, lane = tid & 31;
    const int wm = wid & 3, wn = wid >> 2;
    const int g = lane >> 2, q = lane & 3;
    const int srow = tid >> 2, sq4 = tid & 3;

    float acc[4][8][4];
    #pragma unroll
    for (int i=0;i<4;i++)
        #pragma unroll
        for (int j=0;j<8;j++)
            #pragma unroll
            for (int r=0;r<4;r++) acc[i][j][r] = 0.f;

    #define HSTAGE_A(buf, k0) { \
        _Pragma("unroll") \
        for (int i = 0; i < 4; i++) { \
            int row = srow + 64*i; \
            uint2 v = make_uint2(0u, 0u); \
            if (bm + row < M) v = *(const uint2*)(A + (size_t)(bm+row)*lda + (k0) + sq4*4); \
            As2[buf][sq4*2+0][row] = v.x; \
            As2[buf][sq4*2+1][row] = v.y; \
        } }
    #define HSTAGE_B(buf, k0) { \
        _Pragma("unroll") \
        for (int i = 0; i < 2; i++) { \
            int row = srow + 64*i; \
            uint2 v = *(const uint2*)(W + (size_t)(bn+row)*K + (k0) + sq4*4); \
            Bs2[buf][sq4*2+0][row] = v.x; \
            Bs2[buf][sq4*2+1][row] = v.y; \
        } }

    HSTAGE_A(0, 0)
    HSTAGE_B(0, 0)
    __syncthreads();

    const int nit = K >> 4;
    int buf = 0;
    for (int it = 0; it < nit; it++) {
        uint2 pa[4], pb[2];
        const bool more = (it + 1 < nit);
        if (more) {
            int k0 = (it + 1) << 4;
            #pragma unroll
            for (int i = 0; i < 4; i++) {
                int row = srow + 64*i;
                pa[i] = make_uint2(0u, 0u);
                if (bm + row < M) pa[i] = *(const uint2*)(A + (size_t)(bm+row)*lda + k0 + sq4*4);
            }
            #pragma unroll
            for (int i = 0; i < 2; i++) {
                int row = srow + 64*i;
                pb[i] = *(const uint2*)(W + (size_t)(bn+row)*K + k0 + sq4*4);
            }
        }
        {
            unsigned af[4][4];
            #pragma unroll
            for (int mt=0; mt<4; mt++){
                int mb = wm*64 + mt*16;
                af[mt][0] = As2[buf][q  ][mb+g  ];
                af[mt][1] = As2[buf][q  ][mb+g+8];
                af[mt][2] = As2[buf][q+4][mb+g  ];
                af[mt][3] = As2[buf][q+4][mb+g+8];
            }
            unsigned bf[8][2];
            #pragma unroll
            for (int nt=0; nt<8; nt++){
                int nb = wn*64 + nt*8;
                bf[nt][0] = Bs2[buf][q  ][nb+g];
                bf[nt][1] = Bs2[buf][q+4][nb+g];
            }
            #pragma unroll
            for (int mt=0; mt<4; mt++)
                #pragma unroll
                for (int nt=0; nt<8; nt++)
                    mma16h(acc[mt][nt], af[mt], bf[nt]);
        }
        if (more) {
            int nb2 = buf ^ 1;
            #pragma unroll
            for (int i = 0; i < 4; i++) {
                int row = srow + 64*i;
                As2[nb2][sq4*2+0][row] = pa[i].x;
                As2[nb2][sq4*2+1][row] = pa[i].y;
            }
            #pragma unroll
            for (int i = 0; i < 2; i++) {
                int row = srow + 64*i;
                Bs2[nb2][sq4*2+0][row] = pb[i].x;
                Bs2[nb2][sq4*2+1][row] = pb[i].y;
            }
            __syncthreads();
            buf = nb2;
        }
    }
    const int ldc = dsc.ldc;
    #pragma unroll
    for (int nt=0; nt<8; nt++) {
        int c = bn + wn*64 + nt*8 + q*2;
        float2 bv = make_float2(0.f, 0.f);
        if (dsc.bias) bv = *(const float2*)(dsc.bias + c);
        #pragma unroll
        for (int mt=0; mt<4; mt++) {
            int r0 = bm + wm*64 + mt*16 + g;
            if (r0 < M) {
                float ox = acc[mt][nt][0]+bv.x, oy = acc[mt][nt][1]+bv.y;
                if (dsc.ohalf) *(__half2*)(dsc.Ch + (size_t)r0*ldc + c) = __floats2half2_rn(ox, oy);
                else           *(float2*)(dsc.Cf + (size_t)r0*ldc + c) = make_float2(ox, oy);
            }
            if (r0 + 8 < M) {
                float ox = acc[mt][nt][2]+bv.x, oy = acc[mt][nt][3]+bv.y;
                if (dsc.ohalf) *(__half2*)(dsc.Ch + (size_t)(r0+8)*ldc + c) = __floats2half2_rn(ox, oy);
                else           *(float2*)(dsc.Cf + (size_t)(r0+8)*ldc + c) = make_float2(ox, oy);
            }
        }
    }
}

// ---------- wigner: msg = perm(wigner @ [x_src|x_dst]) * rad ----------------
__global__ void k_wigner(const float* __restrict__ x, const int* __restrict__ ei,
                         const float* __restrict__ wig, const __half* __restrict__ rad,
                         __half* __restrict__ sm)
{
    __shared__ __align__(16) float wg[19][28];
    int e = blockIdx.x;
    int t = threadIdx.x; // 128
    int src = ei[e], dst = ei[NE + e];
    const float* xp = (t < 64) ? (x + (size_t)src*1600) : (x + (size_t)dst*1600);
    int c = t & 63;
    float msg[28];
    #pragma unroll
    for (int j = 0; j < 25; j++) msg[j] = xp[j*64 + c];
    msg[25] = 0.f; msg[26] = 0.f; msg[27] = 0.f;
    for (int i = t; i < 475; i += 128) {
        int p = i/25, j = i%25;
        wg[p][j] = wig[(size_t)e*475 + (size_t)c_PERM[p]*25 + j];
    }
    for (int i = t; i < 57; i += 128) {          // zero the 3-pad per row
        int p = i/3, j = 25 + i%3;
        wg[p][j] = 0.f;
    }
    __syncthreads();
    const __half* re = rad + (size_t)e*1536;
    __half* so = sm + (size_t)e*2432;
    #pragma unroll
    for (int p = 0; p < 19; p++) {
        float acc = 0.f;
        #pragma unroll
        for (int j4 = 0; j4 < 7; j4++) {
            float4 w4 = *(const float4*)&wg[p][j4*4];
            acc += w4.x*msg[j4*4+0] + w4.y*msg[j4*4+1]
                 + w4.z*msg[j4*4+2] + w4.w*msg[j4*4+3];
        }
        so[p*128 + t] = __float2half_rn(acc * __half2float(re[c_RADOFF[p] + t]));
    }
}

// ---------- grid stage: silu-gated S2 pointwise (reg-h + float4 LDS) --------
__global__ void k_grid(const float* __restrict__ tmp0, const __half* __restrict__ h1,
                       const float* __restrict__ tgrid, const float* __restrict__ fgrid,
                       __half* __restrict__ h2)
{
    __shared__ __align__(16) float tg[100][20];
    __shared__ __align__(16) float fg[100][20];
    int t = threadIdx.x; // 128
    for (int i = t; i < 1900; i += 128) {
        int ba = i / 19, p = i % 19;
        tg[ba][p] = tgrid[ba*19 + c_PERM[p]];
        fg[ba][p] = fgrid[ba*19 + c_PERM[p]];
    }
    for (int i = t; i < 100; i += 128) { tg[i][19] = 0.f; fg[i][19] = 0.f; }
    int el = t >> 6, c = t & 63;
    int e = blockIdx.x*2 + el;
    const float* t0 = tmp0 + (size_t)e*896;
    float hreg[20];
    #pragma unroll
    for (int p = 0; p < 5; p++) hreg[p] = t0[576 + p*64 + c];
    const __half* hh = h1 + (size_t)e*1216;
    #pragma unroll
    for (int p = 5; p < 19; p++) hreg[p] = __half2float(hh[p*64 + c]);
    hreg[19] = 0.f;
    __syncthreads();
    float s2[20];
    #pragma unroll
    for (int p=0;p<20;p++) s2[p]=0.f;
    for (int ba = 0; ba < 100; ba++) {
        float g = 0.f;
        #pragma unroll
        for (int p4 = 0; p4 < 5; p4++) {
            float4 tp = *(const float4*)&tg[ba][4*p4];
            g += tp.x*hreg[4*p4] + tp.y*hreg[4*p4+1] + tp.z*hreg[4*p4+2] + tp.w*hreg[4*p4+3];
        }
        g = siluf_(g);
        #pragma unroll
        for (int p4 = 0; p4 < 5; p4++) {
            float4 fp = *(const float4*)&fg[ba][4*p4];
            s2[4*p4]   += fp.x * g;
            s2[4*p4+1] += fp.y * g;
            s2[4*p4+2] += fp.z * g;
            s2[4*p4+3] += fp.w * g;
        }
    }
    __half* o = h2 + (size_t)e*1216;
    o[c] = __float2half_rn(siluf_(t0[512 + c]));    // row 0 := silu(gate)
    #pragma unroll
    for (int p = 1; p < 19; p++) o[p*64 + c] = __float2half_rn(s2[p]);
}

// ---------- alpha logits: LN + smooth-leaky-relu + dot ----------------------
__global__ void k_alpha1(const float* __restrict__ tmp0,
                         const float* __restrict__ lng, const float* __restrict__ lnb,
                         const float* __restrict__ adot,
                         float* __restrict__ alpha)
{
    int e = blockIdx.x;
    int w = threadIdx.x >> 5, lane = threadIdx.x & 31; // 8 warps = 8 heads
    const float* a = tmp0 + (size_t)e*896 + w*64;
    float v0 = a[lane], v1 = a[lane+32];
    float s = v0+v1;
    #pragma unroll
    for (int o=16;o;o>>=1) s += __shfl_xor_sync(0xffffffffu, s, o);
    float mu = s * (1.f/64.f);
    float d0=v0-mu, d1=v1-mu;
    float q = d0*d0+d1*d1;
    #pragma unroll
    for (int o=16;o;o>>=1) q += __shfl_xor_sync(0xffffffffu, q, o);
    float rstd = rsqrtf(q*(1.f/64.f) + 1e-5f);
    float x0 = slrelu_(d0*rstd*lng[lane]+lnb[lane]);
    float x1 = slrelu_(d1*rstd*lng[lane+32]+lnb[lane+32]);
    float p = x0*adot[w*64+lane] + x1*adot[w*64+lane+32];
    #pragma unroll
    for (int o=16;o;o>>=1) p += __shfl_xor_sync(0xffffffffu, p, o);
    if (lane == 0) alpha[e*8+w] = p;
}

// ---------- per-node attention: softmax + wigner_inv + direct sum -----------
__global__ void k_attn(const __half* __restrict__ h3, const float* __restrict__ winv,
                       const float* __restrict__ alpha,
                       const int* __restrict__ cnt, const int* __restrict__ csr,
                       float* __restrict__ node)
{
    __shared__ __align__(16) float wi[25][20];
    __shared__ float wt8[8];
    __shared__ float mx[8], dn[8];
    int n = blockIdx.x, t = threadIdx.x; // 128
    int off = cnt[n], deg = cnt[n+1] - off;
    // warp-parallel softmax precompute: 16 lanes per head
    {
        int h = t >> 4, l = t & 15;
        float m = -1e30f;
        for (int i = l; i < deg; i += 16)
            m = fmaxf(m, alpha[csr[off+i]*8 + h]);
        #pragma unroll
        for (int o = 8; o; o >>= 1)
            m = fmaxf(m, __shfl_xor_sync(0xffffffffu, m, o, 16));
        float s = 0.f;
        for (int i = l; i < deg; i += 16)
            s += __expf(alpha[csr[off+i]*8 + h] - m);
        #pragma unroll
        for (int o = 8; o; o >>= 1)
            s += __shfl_xor_sync(0xffffffffu, s, o, 16);
        if (l == 0) { mx[h] = m; dn[h] = s; }
    }
    if (t < 25) wi[t][19] = 0.f;      // zero pad column
    __syncthreads();
    float acc[25];
    #pragma unroll
    for (int r = 0; r < 25; r++) acc[r] = 0.f;
    for (int i = 0; i < deg; i++) {
        int e = csr[off + i];
        for (int j = t; j < 475; j += 128) {
            int r = j/19, p = j%19;
            wi[r][p] = winv[(size_t)e*475 + r*19 + c_PERM[p]];
        }
        if (t < 8) wt8[t] = __expf(alpha[e*8+t] - mx[t]) / (dn[t] + 1e-16f);
        __syncthreads();
        float w = wt8[t >> 4];
        const __half* hh = h3 + (size_t)e*2432;
        float m[20];
        #pragma unroll
        for (int p = 0; p < 19; p++) m[p] = __half2float(hh[p*128 + t]) * w;
        m[19] = 0.f;
        #pragma unroll
        for (int r = 0; r < 25; r++) {
            float a = 0.f;
            #pragma unroll
            for (int p4 = 0; p4 < 5; p4++) {
                float4 w4 = *(const float4*)&wi[r][4*p4];
                a += w4.x*m[4*p4] + w4.y*m[4*p4+1] + w4.z*m[4*p4+2] + w4.w*m[4*p4+3];
            }
            acc[r] += a;
        }
        __syncthreads();
    }
    float* no = node + (size_t)n*3200;
    #pragma unroll
    for (int r = 0; r < 25; r++) no[r*128 + t] = acc[r];
}

// ---------- output projection ----------------------------------------------
__global__ void k_proj(const float* __restrict__ node, const float* __restrict__ pw,
                       const float* __restrict__ pb, float* __restrict__ outp)
{
    __shared__ float wt[128*65];
    int bid = blockIdx.x;      // n*5 + l
    int n = bid / 5, l = bid % 5;
    int t = threadIdx.x;       // 64
    for (int i = t; i < 8192; i += 64) {
        int o = i >> 7, c = i & 127;
        wt[c*65 + o] = pw[l*8192 + i];
    }
    __syncthreads();
    int i0 = l*l, i1 = (l+1)*(l+1);
    for (int i = i0; i < i1; i++) {
        const float* nr = node + (size_t)n*3200 + i*128;
        float acc = (i == 0) ? pb[t] : 0.f;
        #pragma unroll 8
        for (int c = 0; c < 128; c++) acc += nr[c] * wt[c*65 + t];
        outp[(size_t)n*1600 + i*64 + t] = acc;
    }
}

// ----------------------------------------------------------------------------
extern "C" void kernel_launch(void* const* d_in, const int* in_sizes, int n_in,
                              void* d_out, int out_size)
{
    const float* x    = (const float*)d_in[0];
    const float* ed   = (const float*)d_in[1];
    const int*   ei   = (const int*)  d_in[2];
    const float* wig  = (const float*)d_in[3];
    const float* winv = (const float*)d_in[4];
    const float* tgr  = (const float*)d_in[5];
    const float* fgr  = (const float*)d_in[6];
    const float* rw1  = (const float*)d_in[7];
    const float* rb1  = (const float*)d_in[8];
    const float* rg1  = (const float*)d_in[9];
    const float* rbe1 = (const float*)d_in[10];
    const float* rw2  = (const float*)d_in[11];
    const float* rb2  = (const float*)d_in[12];
    const float* rg2  = (const float*)d_in[13];
    const float* rbe2 = (const float*)d_in[14];
    const float* rw3  = (const float*)d_in[15];
    const float* rb3  = (const float*)d_in[16];
    const float* c1w0 = (const float*)d_in[17];
    const float* c1b0 = (const float*)d_in[18];
    const float* c1w1 = (const float*)d_in[19];
    const float* c1w2 = (const float*)d_in[20];
    const float* c2w0 = (const float*)d_in[21];
    const float* c2b0 = (const float*)d_in[22];
    const float* c2w1 = (const float*)d_in[23];
    const float* c2w2 = (const float*)d_in[24];
    const float* alng = (const float*)d_in[25];
    const float* alnb = (const float*)d_in[26];
    const float* adot = (const float*)d_in[27];
    const float* pw   = (const float*)d_in[28];
    const float* pb   = (const float*)d_in[29];
    float* outp = (float*)d_out;

    void* p;
    cudaGetSymbolAddress(&p, g_hid);  __half* hid = (__half*)p;
    cudaGetSymbolAddress(&p, g_rad);  __half* rad = (__half*)p;
    cudaGetSymbolAddress(&p, g_sm);   __half* sm  = (__half*)p;
    cudaGetSymbolAddress(&p, g_tmp0); float* tmp0 = (float*)p;
    cudaGetSymbolAddress(&p, g_h1);   __half* h1  = (__half*)p;
    cudaGetSymbolAddress(&p, g_h2);   __half* h2  = (__half*)p;
    cudaGetSymbolAddress(&p, g_h3);   __half* h3  = (__half*)p;
    cudaGetSymbolAddress(&p, g_alf);  float* alf  = (float*)p;
    cudaGetSymbolAddress(&p, g_node); float* node = (float*)p;
    cudaGetSymbolAddress(&p, g_wp);   __half* wp  = (__half*)p;
    cudaGetSymbolAddress(&p, g_cnt);  int* cnt = (int*)p;
    cudaGetSymbolAddress(&p, g_cur);  int* cur = (int*)p;
    cudaGetSymbolAddress(&p, g_csr);  int* csr = (int*)p;

    cudaFuncSetAttribute(k_gemm_m, cudaFuncAttributeMaxDynamicSharedMemorySize, GH_SMEM);

    const int MB = (NE + 255) / 256;   // 79
    const int BIG = 0x3fffffff;

    // CSR by destination
    k_zeroc<<<(NN + 256)/256, 256>>>(cnt);
    k_count<<<(NE + 255)/256, 256>>>(ei, cnt);
    k_scan<<<1, 1024>>>(cnt, cur);
    k_scatter<<<(NE + 255)/256, 256>>>(ei, cur, csr);

    // weight prep (fp16 round; complex weights expanded to real form)
    k_cvtw<<<(98304+255)/256, 256>>>(rw3,  wp + WP_RAD,  98304);
    k_cvtw<<<(573440+255)/256, 256>>>(c1w0, wp + WP_C1G0, 573440);
    k_cvtw<<<(204800+255)/256, 256>>>(c2w0, wp + WP_C2G0, 204800);
    k_prepw<<<(256*512+255)/256, 256>>>(c1w1, wp + WP_C1M1, 256, 512);
    k_prepw<<<(192*384+255)/256, 256>>>(c1w2, wp + WP_C1M2, 192, 384);
    k_prepw<<<(512*256+255)/256, 256>>>(c2w1, wp + WP_C2M1, 512, 256);
    k_prepw<<<(384*192+255)/256, 256>>>(c2w2, wp + WP_C2M2, 384, 192);

    k_radial<<<512, 64>>>(ed, rw1, rb1, rg1, rbe1, rw2, rb2, rg2, rbe2, hid);

    // radial layer 3 (fp16 out)
    {
        GPack gp{};
        gp.d[0] = GDesc{hid, wp + WP_RAD, rb3, rad, nullptr, 64, 1536, 64, 1};
        gp.cum1 = BIG; gp.cum2 = BIG;
        k_gemm_m<<<dim3(12, MB), 256, GH_SMEM>>>(gp, NE);
    }
    k_wigner<<<NE, 128>>>(x, ei, wig, rad, sm);
    // conv1: 3 gemms merged
    {
        GPack gp{};
        gp.d[0] = GDesc{sm,      wp + WP_C1G0, c1b0,    nullptr, tmp0, 2432, 896, 640, 0};
        gp.d[1] = GDesc{sm+640,  wp + WP_C1M1, nullptr, h1+320, nullptr, 2432, 1216, 1024, 1};
        gp.d[2] = GDesc{sm+1664, wp + WP_C1M2, nullptr, h1+832, nullptr, 2432, 1216, 768, 1};
        gp.cum1 = 7; gp.cum2 = 11;
        k_gemm_m<<<dim3(14, MB), 256, GH_SMEM>>>(gp, NE);
    }
    k_grid<<<NE/2, 128>>>(tmp0, h1, tgr, fgr, h2);
    // conv2: 3 gemms merged
    {
        GPack gp{};
        gp.d[0] = GDesc{h2,     wp + WP_C2G0, c2b0,    h3,      nullptr, 1216, 2432, 320, 1};
        gp.d[1] = GDesc{h2+320, wp + WP_C2M1, nullptr, h3+640,  nullptr, 1216, 2432, 512, 1};
        gp.d[2] = GDesc{h2+832, wp + WP_C2M2, nullptr, h3+1664, nullptr, 1216, 2432, 384, 1};
        gp.cum1 = 5; gp.cum2 = 13;
        k_gemm_m<<<dim3(19, MB), 256, GH_SMEM>>>(gp, NE);
    }
    // attention (per-node, no atomics)
    k_alpha1<<<NE, 256>>>(tmp0, alng, alnb, adot, alf);
    k_attn<<<NN, 128>>>(h3, winv, alf, cnt, csr, node);
    // projection
    k_proj<<<NN*5, 64>>>(node, pw, pb, outp);
}

// round 17
// speedup vs baseline: 1.0550x; 1.0432x over previous
#include <cuda_runtime.h>
#include <cuda_fp16.h>
#include <cuda_bf16.h>
#include <cstdint>

#define NE 20000
#define NN 1000

// permuted row order: m=0 rows(5), +1(4), -1(4), +2(3), -2(3)
__constant__ int c_PERM[19]   = {0,2,6,11,16, 3,7,12,17, 1,5,10,15, 8,13,18, 4,9,14};
__constant__ int c_RADOFF[19] = {0,128,256,384,512, 640,768,896,1024, 640,768,896,1024,
                                 1152,1280,1408, 1152,1280,1408};

// ----------------- scratch (__device__ globals; no runtime alloc) -----------
__device__ __align__(16) __half g_hid [(size_t)NE*64];
__device__ __align__(16) __half g_rad [(size_t)NE*1536];
__device__ __align__(16) __half g_sm  [(size_t)NE*2432];
__device__ __align__(16) float  g_tmp0[(size_t)NE*896];
__device__ __align__(16) __half g_h1  [(size_t)NE*1216];
__device__ __align__(16) __half g_h2  [(size_t)NE*1216];
__device__ __align__(16) __half g_h3  [(size_t)NE*2432];
__device__ __align__(16) float  g_alf [(size_t)NE*8];
__device__ __align__(16) float  g_node[(size_t)NN*3200];
__device__ int g_cnt[NN+1];
__device__ int g_cur[NN];
__device__ int g_csr[NE];
// fp16-prepped weights (plain + complex-expanded)
__device__ __align__(16) __half g_wp [2514944];

#define WP_RAD   0
#define WP_C1G0  98304
#define WP_C1M1  671744
#define WP_C1M2  1196032
#define WP_C2G0  1490944
#define WP_C2M1  1695744
#define WP_C2M2  2220032

// ----------------- helpers --------------------------------------------------
__device__ __forceinline__ float sigmoidf_(float x){ return 1.f/(1.f+__expf(-x)); }
__device__ __forceinline__ float siluf_(float x){ return x*sigmoidf_(x); }
__device__ __forceinline__ float slrelu_(float x){ return 0.6f*x + 0.4f*x*(2.f*sigmoidf_(x)-1.f); }

__device__ __forceinline__ uint32_t s2u32_(const void* p){
    uint32_t a;
    asm("{ .reg .u64 t; cvta.to.shared.u64 t, %1; cvt.u32.u64 %0, t; }" : "=r"(a) : "l"(p));
    return a;
}
__device__ __forceinline__ void cpasync16(uint32_t dst, const void* src){
    asm volatile("cp.async.cg.shared.global [%0], [%1], 16;" :: "r"(dst), "l"(src));
}
#define CP_COMMIT() asm volatile("cp.async.commit_group;" ::: "memory")
#define CP_WAIT1()  asm volatile("cp.async.wait_group 1;" ::: "memory")

__device__ __forceinline__ void mma16h(float* d, const unsigned* a, const unsigned* b){
    asm("mma.sync.aligned.m16n8k16.row.col.f32.f16.f16.f32 "
        "{%0,%1,%2,%3}, {%4,%5,%6,%7}, {%8,%9}, {%0,%1,%2,%3};"
        : "+f"(d[0]), "+f"(d[1]), "+f"(d[2]), "+f"(d[3])
        : "r"(a[0]), "r"(a[1]), "r"(a[2]), "r"(a[3]), "r"(b[0]), "r"(b[1]));
}

__device__ __forceinline__ float red64(float v, float* sbuf, int t){
    #pragma unroll
    for (int o=16;o;o>>=1) v += __shfl_xor_sync(0xffffffffu, v, o);
    if ((t&31)==0) sbuf[t>>5] = v;
    __syncthreads();
    float r = sbuf[0]+sbuf[1];
    __syncthreads();
    return r;
}

// ----------------- CSR build ------------------------------------------------
__global__ void k_zeroc(int* cnt){
    int i = blockIdx.x*256 + threadIdx.x;
    if (i <= NN) cnt[i] = 0;
}
__global__ void k_count(const int* __restrict__ ei, int* cnt){
    int i = blockIdx.x*256 + threadIdx.x;
    if (i < NE) atomicAdd(&cnt[ei[NE + i]], 1);
}
__global__ void k_scan(int* cnt, int* cur){
    __shared__ int s[1024];
    int t = threadIdx.x;
    int v = (t < NN) ? cnt[t] : 0;
    s[t] = v;
    __syncthreads();
    for (int o = 1; o < 1024; o <<= 1) {
        int x = (t >= o) ? s[t - o] : 0;
        __syncthreads();
        s[t] += x;
        __syncthreads();
    }
    int incl = s[t];
    if (t < NN) { cnt[t] = incl - v; cur[t] = incl - v; }
    if (t == NN - 1) cnt[NN] = incl;
}
__global__ void k_scatter(const int* __restrict__ ei, int* cur, int* csr){
    int i = blockIdx.x*256 + threadIdx.x;
    if (i < NE) {
        int pos = atomicAdd(&cur[ei[NE + i]], 1);
        csr[pos] = i;
    }
}

// ----------------- weight prep ----------------------------------------------
__global__ void k_cvtw(const float* __restrict__ w, __half* __restrict__ o, int n){
    int i = blockIdx.x*256 + threadIdx.x;
    if (i < n) o[i] = __float2half_rn(w[i]);
}
__global__ void k_prepw(const float* __restrict__ w, __half* __restrict__ wp, int N, int K){
    int i = blockIdx.x*256 + threadIdx.x;
    if (i >= N*K) return;
    int n = i / K, k = i % K;
    float wr = w[(size_t)n*K + k];
    float wi = w[(size_t)(N+n)*K + k];
    size_t row0 = (size_t)n*2*K, row1 = (size_t)(N+n)*2*K;
    wp[row0 + k]     = __float2half_rn(wr);
    wp[row0 + K + k] = __float2half_rn(-wi);
    wp[row1 + k]     = __float2half_rn(wi);
    wp[row1 + K + k] = __float2half_rn(wr);
}

// ----------------- radial layers 1+2 (LN + silu) ----------------------------
__global__ void k_radial(const float* __restrict__ ed,
                         const float* __restrict__ w1, const float* __restrict__ b1,
                         const float* __restrict__ g1, const float* __restrict__ be1,
                         const float* __restrict__ w2, const float* __restrict__ b2,
                         const float* __restrict__ g2, const float* __restrict__ be2,
                         __half* __restrict__ outp)
{
    __shared__ float w1t[64*64], w2t[64*64];
    __shared__ float xin[64], hmid[64];
    __shared__ float sbuf[2];
    int t = threadIdx.x; // 64
    for (int i = t; i < 4096; i += 64) {
        int r = i >> 6, c = i & 63;
        w1t[c*64 + r] = w1[i];
        w2t[c*64 + r] = w2[i];
    }
    __syncthreads();
    for (int e = blockIdx.x; e < NE; e += gridDim.x) {
        xin[t] = ed[(size_t)e*64 + t];
        __syncthreads();
        float acc = b1[t];
        #pragma unroll 8
        for (int k = 0; k < 64; k++) acc += xin[k]*w1t[k*64+t];
        float mu = red64(acc, sbuf, t) * (1.f/64.f);
        float d = acc - mu;
        float var = red64(d*d, sbuf, t) * (1.f/64.f);
        float v = d*rsqrtf(var+1e-5f)*g1[t] + be1[t];
        hmid[t] = siluf_(v);
        __syncthreads();
        acc = b2[t];
        #pragma unroll 8
        for (int k = 0; k < 64; k++) acc += hmid[k]*w2t[k*64+t];
        mu = red64(acc, sbuf, t) * (1.f/64.f);
        d = acc - mu;
        var = red64(d*d, sbuf, t) * (1.f/64.f);
        v = d*rsqrtf(var+1e-5f)*g2[t] + be2[t];
        outp[(size_t)e*64 + t] = __float2half_rn(siluf_(v));
        __syncthreads();
    }
}

// ======= merged fp16 tensor-core GEMM (cp.async 3-stage + ldmatrix) =========
struct GDesc {
    const __half* A; const __half* W; const float* bias;
    __half* Ch; float* Cf;
    int lda, ldc, K, ohalf;
};
struct GPack { GDesc d[3]; int cum1, cum2; };

// stage layout: A[s] at s*8192 (256 rows x 32B swizzled), B[s] at 24576+s*4096
#define GH_SMEM 36864

__global__ void __launch_bounds__(256) k_gemm_m(GPack gp, int M)
{
    extern __shared__ __align__(16) char smem[];
    const uint32_t sb = s2u32_(smem);
    const int tid = threadIdx.x;
    const int x = blockIdx.x;
    const int gi = (x >= gp.cum1) + (x >= gp.cum2);
    const GDesc dsc = gp.d[gi];
    const int base = gi == 0 ? 0 : (gi == 1 ? gp.cum1 : gp.cum2);
    const int bm = blockIdx.y*256, bn = (x - base)*128;
    const __half* __restrict__ A = dsc.A;
    const __half* __restrict__ W = dsc.W;
    const int lda = dsc.lda, K = dsc.K;
    const int wid = tid >> 5, lane = tid & 31;
    const int wm = wid & 3, wn = wid >> 2;
    const int g = lane >> 2, q = lane & 3;

    float acc[4][8][4];
    #pragma unroll
    for (int i=0;i<4;i++)
        #pragma unroll
        for (int j=0;j<8;j++)
            #pragma unroll
            for (int r=0;r<4;r++) acc[i][j][r] = 0.f;

    // ldmatrix per-lane offsets (A: x4 over m16xk16; B: x2 over n8xk16)
    const int a_row = wm*64 + (lane&7) + ((lane>>3)&1)*8;
    const uint32_t a_off = (uint32_t)a_row*32 + (((lane>>4) ^ ((lane>>2)&1))<<4);
    const int b_row = wn*64 + (lane&7);
    const uint32_t b_off = (uint32_t)b_row*32 + ((((lane>>3)&1) ^ ((lane>>2)&1))<<4);

    // cp.async staging indices
    const int ar0 = tid >> 1, ac0 = tid & 1;              // A: rows 0..127 (+128 second pass)
    const int br  = tid >> 1, bc  = tid & 1;              // B: rows 0..127

    #define GISSUE(s, k0) { \
        _Pragma("unroll") \
        for (int i = 0; i < 2; i++) { \
            int row = ar0 + 128*i, c = ac0; \
            uint32_t off = (uint32_t)(s)*8192 + (uint32_t)row*32 + ((c ^ ((row>>2)&1))<<4); \
            int gr = bm + row; \
            if (gr < M) cpasync16(sb + off, A + (size_t)gr*lda + (k0) + c*8); \
            else *(uint4*)(smem + off) = make_uint4(0u,0u,0u,0u); \
        } \
        { \
            uint32_t off = 24576u + (uint32_t)(s)*4096 + (uint32_t)br*32 + ((bc ^ ((br>>2)&1))<<4); \
            cpasync16(sb + off, W + (size_t)(bn+br)*K + (k0) + bc*8); \
        } }

    const int nit = K >> 4;
    GISSUE(0, 0)
    CP_COMMIT();
    if (nit > 1) { GISSUE(1, 16) }
    CP_COMMIT();

    for (int it = 0; it < nit; it++) {
        CP_WAIT1();
        __syncthreads();
        int s = it % 3;
        uint32_t aS = sb + (uint32_t)s*8192;
        uint32_t bS = sb + 24576u + (uint32_t)s*4096;
        unsigned af[4][4], bf[8][2];
        #pragma unroll
        for (int mt=0; mt<4; mt++)
            asm volatile("ldmatrix.sync.aligned.m8n8.x4.shared.b16 {%0,%1,%2,%3}, [%4];"
                : "=r"(af[mt][0]), "=r"(af[mt][1]), "=r"(af[mt][2]), "=r"(af[mt][3])
                : "r"(aS + a_off + mt*512));
        #pragma unroll
        for (int nt=0; nt<8; nt++)
            asm volatile("ldmatrix.sync.aligned.m8n8.x2.shared.b16 {%0,%1}, [%2];"
                : "=r"(bf[nt][0]), "=r"(bf[nt][1])
                : "r"(bS + b_off + nt*256));
        #pragma unroll
        for (int mt=0; mt<4; mt++)
            #pragma unroll
            for (int nt=0; nt<8; nt++)
                mma16h(acc[mt][nt], af[mt], bf[nt]);
        int nx = it + 2;
        if (nx < nit) { GISSUE(nx % 3, nx << 4) }
        CP_COMMIT();
    }

    const int ldc = dsc.ldc;
    #pragma unroll
    for (int nt=0; nt<8; nt++) {
        int c = bn + wn*64 + nt*8 + q*2;
        float2 bv = make_float2(0.f, 0.f);
        if (dsc.bias) bv = *(const float2*)(dsc.bias + c);
        #pragma unroll
        for (int mt=0; mt<4; mt++) {
            int r0 = bm + wm*64 + mt*16 + g;
            if (r0 < M) {
                float ox = acc[mt][nt][0]+bv.x, oy = acc[mt][nt][1]+bv.y;
                if (dsc.ohalf) *(__half2*)(dsc.Ch + (size_t)r0*ldc + c) = __floats2half2_rn(ox, oy);
                else           *(float2*)(dsc.Cf + (size_t)r0*ldc + c) = make_float2(ox, oy);
            }
            if (r0 + 8 < M) {
                float ox = acc[mt][nt][2]+bv.x, oy = acc[mt][nt][3]+bv.y;
                if (dsc.ohalf) *(__half2*)(dsc.Ch + (size_t)(r0+8)*ldc + c) = __floats2half2_rn(ox, oy);
                else           *(float2*)(dsc.Cf + (size_t)(r0+8)*ldc + c) = make_float2(ox, oy);
            }
        }
    }
}

// ---------- wigner: msg = perm(wigner @ [x_src|x_dst]) * rad ----------------
__global__ void k_wigner(const float* __restrict__ x, const int* __restrict__ ei,
                         const float* __restrict__ wig, const __half* __restrict__ rad,
                         __half* __restrict__ sm)
{
    __shared__ __align__(16) float wg[19][28];
    int e = blockIdx.x;
    int t = threadIdx.x; // 128
    int src = ei[e], dst = ei[NE + e];
    const float* xp = (t < 64) ? (x + (size_t)src*1600) : (x + (size_t)dst*1600);
    int c = t & 63;
    float msg[28];
    #pragma unroll
    for (int j = 0; j < 25; j++) msg[j] = xp[j*64 + c];
    msg[25] = 0.f; msg[26] = 0.f; msg[27] = 0.f;
    for (int i = t; i < 475; i += 128) {
        int p = i/25, j = i%25;
        wg[p][j] = wig[(size_t)e*475 + (size_t)c_PERM[p]*25 + j];
    }
    for (int i = t; i < 57; i += 128) {
        int p = i/3, j = 25 + i%3;
        wg[p][j] = 0.f;
    }
    __syncthreads();
    const __half* re = rad + (size_t)e*1536;
    __half* so = sm + (size_t)e*2432;
    #pragma unroll
    for (int p = 0; p < 19; p++) {
        float acc = 0.f;
        #pragma unroll
        for (int j4 = 0; j4 < 7; j4++) {
            float4 w4 = *(const float4*)&wg[p][j4*4];
            acc += w4.x*msg[j4*4+0] + w4.y*msg[j4*4+1]
                 + w4.z*msg[j4*4+2] + w4.w*msg[j4*4+3];
        }
        so[p*128 + t] = __float2half_rn(acc * __half2float(re[c_RADOFF[p] + t]));
    }
}

// ---------- grid stage: silu-gated S2 pointwise (reg-h + float4 LDS) --------
__global__ void k_grid(const float* __restrict__ tmp0, const __half* __restrict__ h1,
                       const float* __restrict__ tgrid, const float* __restrict__ fgrid,
                       __half* __restrict__ h2)
{
    __shared__ __align__(16) float tg[100][20];
    __shared__ __align__(16) float fg[100][20];
    int t = threadIdx.x; // 128
    for (int i = t; i < 1900; i += 128) {
        int ba = i / 19, p = i % 19;
        tg[ba][p] = tgrid[ba*19 + c_PERM[p]];
        fg[ba][p] = fgrid[ba*19 + c_PERM[p]];
    }
    for (int i = t; i < 100; i += 128) { tg[i][19] = 0.f; fg[i][19] = 0.f; }
    int el = t >> 6, c = t & 63;
    int e = blockIdx.x*2 + el;
    const float* t0 = tmp0 + (size_t)e*896;
    float hreg[20];
    #pragma unroll
    for (int p = 0; p < 5; p++) hreg[p] = t0[576 + p*64 + c];
    const __half* hh = h1 + (size_t)e*1216;
    #pragma unroll
    for (int p = 5; p < 19; p++) hreg[p] = __half2float(hh[p*64 + c]);
    hreg[19] = 0.f;
    __syncthreads();
    float s2[20];
    #pragma unroll
    for (int p=0;p<20;p++) s2[p]=0.f;
    for (int ba = 0; ba < 100; ba++) {
        float g = 0.f;
        #pragma unroll
        for (int p4 = 0; p4 < 5; p4++) {
            float4 tp = *(const float4*)&tg[ba][4*p4];
            g += tp.x*hreg[4*p4] + tp.y*hreg[4*p4+1] + tp.z*hreg[4*p4+2] + tp.w*hreg[4*p4+3];
        }
        g = siluf_(g);
        #pragma unroll
        for (int p4 = 0; p4 < 5; p4++) {
            float4 fp = *(const float4*)&fg[ba][4*p4];
            s2[4*p4]   += fp.x * g;
            s2[4*p4+1] += fp.y * g;
            s2[4*p4+2] += fp.z * g;
            s2[4*p4+3] += fp.w * g;
        }
    }
    __half* o = h2 + (size_t)e*1216;
    o[c] = __float2half_rn(siluf_(t0[512 + c]));    // row 0 := silu(gate)
    #pragma unroll
    for (int p = 1; p < 19; p++) o[p*64 + c] = __float2half_rn(s2[p]);
}

// ---------- alpha logits: LN + smooth-leaky-relu + dot ----------------------
__global__ void k_alpha1(const float* __restrict__ tmp0,
                         const float* __restrict__ lng, const float* __restrict__ lnb,
                         const float* __restrict__ adot,
                         float* __restrict__ alpha)
{
    int e = blockIdx.x;
    int w = threadIdx.x >> 5, lane = threadIdx.x & 31; // 8 warps = 8 heads
    const float* a = tmp0 + (size_t)e*896 + w*64;
    float v0 = a[lane], v1 = a[lane+32];
    float s = v0+v1;
    #pragma unroll
    for (int o=16;o;o>>=1) s += __shfl_xor_sync(0xffffffffu, s, o);
    float mu = s * (1.f/64.f);
    float d0=v0-mu, d1=v1-mu;
    float q = d0*d0+d1*d1;
    #pragma unroll
    for (int o=16;o;o>>=1) q += __shfl_xor_sync(0xffffffffu, q, o);
    float rstd = rsqrtf(q*(1.f/64.f) + 1e-5f);
    float x0 = slrelu_(d0*rstd*lng[lane]+lnb[lane]);
    float x1 = slrelu_(d1*rstd*lng[lane+32]+lnb[lane+32]);
    float p = x0*adot[w*64+lane] + x1*adot[w*64+lane+32];
    #pragma unroll
    for (int o=16;o;o>>=1) p += __shfl_xor_sync(0xffffffffu, p, o);
    if (lane == 0) alpha[e*8+w] = p;
}

// ---------- per-node attention: softmax + wigner_inv + direct sum -----------
__global__ void k_attn(const __half* __restrict__ h3, const float* __restrict__ winv,
                       const float* __restrict__ alpha,
                       const int* __restrict__ cnt, const int* __restrict__ csr,
                       float* __restrict__ node)
{
    __shared__ __align__(16) float wi[25][20];
    __shared__ float wt8[8];
    __shared__ float mx[8], dn[8];
    int n = blockIdx.x, t = threadIdx.x; // 128
    int off = cnt[n], deg = cnt[n+1] - off;
    // warp-parallel softmax precompute: 16 lanes per head
    {
        int h = t >> 4, l = t & 15;
        float m = -1e30f;
        for (int i = l; i < deg; i += 16)
            m = fmaxf(m, alpha[csr[off+i]*8 + h]);
        #pragma unroll
        for (int o = 8; o; o >>= 1)
            m = fmaxf(m, __shfl_xor_sync(0xffffffffu, m, o, 16));
        float s = 0.f;
        for (int i = l; i < deg; i += 16)
            s += __expf(alpha[csr[off+i]*8 + h] - m);
        #pragma unroll
        for (int o = 8; o; o >>= 1)
            s += __shfl_xor_sync(0xffffffffu, s, o, 16);
        if (l == 0) { mx[h] = m; dn[h] = s; }
    }
    if (t < 25) wi[t][19] = 0.f;
    __syncthreads();
    float acc[25];
    #pragma unroll
    for (int r = 0; r < 25; r++) acc[r] = 0.f;
    for (int i = 0; i < deg; i++) {
        int e = csr[off + i];
        for (int j = t; j < 475; j += 128) {
            int r = j/19, p = j%19;
            wi[r][p] = winv[(size_t)e*475 + r*19 + c_PERM[p]];
        }
        if (t < 8) wt8[t] = __expf(alpha[e*8+t] - mx[t]) / (dn[t] + 1e-16f);
        __syncthreads();
        float w = wt8[t >> 4];
        const __half* hh = h3 + (size_t)e*2432;
        float m[20];
        #pragma unroll
        for (int p = 0; p < 19; p++) m[p] = __half2float(hh[p*128 + t]) * w;
        m[19] = 0.f;
        #pragma unroll
        for (int r = 0; r < 25; r++) {
            float a = 0.f;
            #pragma unroll
            for (int p4 = 0; p4 < 5; p4++) {
                float4 w4 = *(const float4*)&wi[r][4*p4];
                a += w4.x*m[4*p4] + w4.y*m[4*p4+1] + w4.z*m[4*p4+2] + w4.w*m[4*p4+3];
            }
            acc[r] += a;
        }
        __syncthreads();
    }
    float* no = node + (size_t)n*3200;
    #pragma unroll
    for (int r = 0; r < 25; r++) no[r*128 + t] = acc[r];
}

// ---------- output projection ----------------------------------------------
__global__ void k_proj(const float* __restrict__ node, const float* __restrict__ pw,
                       const float* __restrict__ pb, float* __restrict__ outp)
{
    __shared__ float wt[128*65];
    int bid = blockIdx.x;      // n*5 + l
    int n = bid / 5, l = bid % 5;
    int t = threadIdx.x;       // 64
    for (int i = t; i < 8192; i += 64) {
        int o = i >> 7, c = i & 127;
        wt[c*65 + o] = pw[l*8192 + i];
    }
    __syncthreads();
    int i0 = l*l, i1 = (l+1)*(l+1);
    for (int i = i0; i < i1; i++) {
        const float* nr = node + (size_t)n*3200 + i*128;
        float acc = (i == 0) ? pb[t] : 0.f;
        #pragma unroll 8
        for (int c = 0; c < 128; c++) acc += nr[c] * wt[c*65 + t];
        outp[(size_t)n*1600 + i*64 + t] = acc;
    }
}

// ----------------------------------------------------------------------------
extern "C" void kernel_launch(void* const* d_in, const int* in_sizes, int n_in,
                              void* d_out, int out_size)
{
    const float* x    = (const float*)d_in[0];
    const float* ed   = (const float*)d_in[1];
    const int*   ei   = (const int*)  d_in[2];
    const float* wig  = (const float*)d_in[3];
    const float* winv = (const float*)d_in[4];
    const float* tgr  = (const float*)d_in[5];
    const float* fgr  = (const float*)d_in[6];
    const float* rw1  = (const float*)d_in[7];
    const float* rb1  = (const float*)d_in[8];
    const float* rg1  = (const float*)d_in[9];
    const float* rbe1 = (const float*)d_in[10];
    const float* rw2  = (const float*)d_in[11];
    const float* rb2  = (const float*)d_in[12];
    const float* rg2  = (const float*)d_in[13];
    const float* rbe2 = (const float*)d_in[14];
    const float* rw3  = (const float*)d_in[15];
    const float* rb3  = (const float*)d_in[16];
    const float* c1w0 = (const float*)d_in[17];
    const float* c1b0 = (const float*)d_in[18];
    const float* c1w1 = (const float*)d_in[19];
    const float* c1w2 = (const float*)d_in[20];
    const float* c2w0 = (const float*)d_in[21];
    const float* c2b0 = (const float*)d_in[22];
    const float* c2w1 = (const float*)d_in[23];
    const float* c2w2 = (const float*)d_in[24];
    const float* alng = (const float*)d_in[25];
    const float* alnb = (const float*)d_in[26];
    const float* adot = (const float*)d_in[27];
    const float* pw   = (const float*)d_in[28];
    const float* pb   = (const float*)d_in[29];
    float* outp = (float*)d_out;

    void* p;
    cudaGetSymbolAddress(&p, g_hid);  __half* hid = (__half*)p;
    cudaGetSymbolAddress(&p, g_rad);  __half* rad = (__half*)p;
    cudaGetSymbolAddress(&p, g_sm);   __half* sm  = (__half*)p;
    cudaGetSymbolAddress(&p, g_tmp0); float* tmp0 = (float*)p;
    cudaGetSymbolAddress(&p, g_h1);   __half* h1  = (__half*)p;
    cudaGetSymbolAddress(&p, g_h2);   __half* h2  = (__half*)p;
    cudaGetSymbolAddress(&p, g_h3);   __half* h3  = (__half*)p;
    cudaGetSymbolAddress(&p, g_alf);  float* alf  = (float*)p;
    cudaGetSymbolAddress(&p, g_node); float* node = (float*)p;
    cudaGetSymbolAddress(&p, g_wp);   __half* wp  = (__half*)p;
    cudaGetSymbolAddress(&p, g_cnt);  int* cnt = (int*)p;
    cudaGetSymbolAddress(&p, g_cur);  int* cur = (int*)p;
    cudaGetSymbolAddress(&p, g_csr);  int* csr = (int*)p;

    cudaFuncSetAttribute(k_gemm_m, cudaFuncAttributeMaxDynamicSharedMemorySize, GH_SMEM);

    const int MB = (NE + 255) / 256;   // 79
    const int BIG = 0x3fffffff;

    // CSR by destination
    k_zeroc<<<(NN + 256)/256, 256>>>(cnt);
    k_count<<<(NE + 255)/256, 256>>>(ei, cnt);
    k_scan<<<1, 1024>>>(cnt, cur);
    k_scatter<<<(NE + 255)/256, 256>>>(ei, cur, csr);

    // weight prep (fp16 round; complex weights expanded to real form)
    k_cvtw<<<(98304+255)/256, 256>>>(rw3,  wp + WP_RAD,  98304);
    k_cvtw<<<(573440+255)/256, 256>>>(c1w0, wp + WP_C1G0, 573440);
    k_cvtw<<<(204800+255)/256, 256>>>(c2w0, wp + WP_C2G0, 204800);
    k_prepw<<<(256*512+255)/256, 256>>>(c1w1, wp + WP_C1M1, 256, 512);
    k_prepw<<<(192*384+255)/256, 256>>>(c1w2, wp + WP_C1M2, 192, 384);
    k_prepw<<<(512*256+255)/256, 256>>>(c2w1, wp + WP_C2M1, 512, 256);
    k_prepw<<<(384*192+255)/256, 256>>>(c2w2, wp + WP_C2M2, 384, 192);

    k_radial<<<512, 64>>>(ed, rw1, rb1, rg1, rbe1, rw2, rb2, rg2, rbe2, hid);

    // radial layer 3 (fp16 out)
    {
        GPack gp{};
        gp.d[0] = GDesc{hid, wp + WP_RAD, rb3, rad, nullptr, 64, 1536, 64, 1};
        gp.cum1 = BIG; gp.cum2 = BIG;
        k_gemm_m<<<dim3(12, MB), 256, GH_SMEM>>>(gp, NE);
    }
    k_wigner<<<NE, 128>>>(x, ei, wig, rad, sm);
    // conv1: 3 gemms merged
    {
        GPack gp{};
        gp.d[0] = GDesc{sm,      wp + WP_C1G0, c1b0,    nullptr, tmp0, 2432, 896, 640, 0};
        gp.d[1] = GDesc{sm+640,  wp + WP_C1M1, nullptr, h1+320, nullptr, 2432, 1216, 1024, 1};
        gp.d[2] = GDesc{sm+1664, wp + WP_C1M2, nullptr, h1+832, nullptr, 2432, 1216, 768, 1};
        gp.cum1 = 7; gp.cum2 = 11;
        k_gemm_m<<<dim3(14, MB), 256, GH_SMEM>>>(gp, NE);
    }
    k_grid<<<NE/2, 128>>>(tmp0, h1, tgr, fgr, h2);
    // conv2: 3 gemms merged
    {
        GPack gp{};
        gp.d[0] = GDesc{h2,     wp + WP_C2G0, c2b0,    h3,      nullptr, 1216, 2432, 320, 1};
        gp.d[1] = GDesc{h2+320, wp + WP_C2M1, nullptr, h3+640,  nullptr, 1216, 2432, 512, 1};
        gp.d[2] = GDesc{h2+832, wp + WP_C2M2, nullptr, h3+1664, nullptr, 1216, 2432, 384, 1};
        gp.cum1 = 5; gp.cum2 = 13;
        k_gemm_m<<<dim3(19, MB), 256, GH_SMEM>>>(gp, NE);
    }
    // attention (per-node, no atomics)
    k_alpha1<<<NE, 256>>>(tmp0, alng, alnb, adot, alf);
    k_attn<<<NN, 128>>>(h3, winv, alf, cnt, csr, node);
    // projection
    k_proj<<<NN*5, 64>>>(node, pw, pb, outp);
}